// round 13
// baseline (speedup 1.0000x reference)
#include <cuda_runtime.h>
#include <cuda_bf16.h>

#define NTOK 4096
#define DMODEL 256
#define NHEAD 8
#define HEADD 32
#define KDIM 256
#define SCALE 0.17677669529663689f
#define LOG2E 1.4426950408889634f
#define SCALE2 (SCALE * LOG2E)

typedef unsigned long long u64;
typedef unsigned int u32;

// Scratch (device globals — no allocation allowed)
__device__ float g_pe[NHEAD * NTOK];           // [h][n]
__device__ float g_att[NTOK * DMODEL];         // attention output fp32
__device__ __nv_bfloat16 g_qb[NTOK * DMODEL];  // Q bf16, PRE-SCALED by SCALE*log2e
__device__ __nv_bfloat16 g_kb[NTOK * DMODEL];  // K bf16 [n][h*32+d]
__device__ __nv_bfloat16 g_vb[NTOK * DMODEL];  // V bf16 [n][h*32+d]

// ---------------- helpers ----------------
__device__ __forceinline__ u32 smem_u32(const void* p) {
  u32 a;
  asm("{ .reg .u64 t; cvta.to.shared.u64 t, %1; cvt.u32.u64 %0, t; }" : "=r"(a) : "l"(p));
  return a;
}
__device__ __forceinline__ u32 tf32cvt(float f) {
  u32 r;
  asm("cvt.rna.tf32.f32 %0, %1;" : "=r"(r) : "f"(f));
  return r;
}
__device__ __forceinline__ float ex2(float x) {
  float y;
  asm("ex2.approx.f32 %0, %1;" : "=f"(y) : "f"(x));
  return y;
}
#define LDSM4(r, addr)                                                        \
  asm volatile("ldmatrix.sync.aligned.m8n8.x4.shared.b16 {%0,%1,%2,%3}, [%4];"\
               : "=r"((r)[0]), "=r"((r)[1]), "=r"((r)[2]), "=r"((r)[3])       \
               : "r"(addr))
#define LDSM4T(r, addr)                                                       \
  asm volatile(                                                               \
      "ldmatrix.sync.aligned.m8n8.x4.trans.shared.b16 {%0,%1,%2,%3}, [%4];"   \
      : "=r"((r)[0]), "=r"((r)[1]), "=r"((r)[2]), "=r"((r)[3])                \
      : "r"(addr))
#define MMA16816(d, a, b0, b1)                                                \
  asm volatile(                                                               \
      "mma.sync.aligned.m16n8k16.row.col.f32.bf16.bf16.f32 "                  \
      "{%0,%1,%2,%3}, {%4,%5,%6,%7}, {%8,%9}, {%0,%1,%2,%3};"                 \
      : "+f"((d)[0]), "+f"((d)[1]), "+f"((d)[2]), "+f"((d)[3])                \
      : "r"((a)[0]), "r"((a)[1]), "r"((a)[2]), "r"((a)[3]), "r"(b0), "r"(b1))
#define MMATF32(d, a, b)                                                      \
  asm volatile(                                                               \
      "mma.sync.aligned.m16n8k8.row.col.f32.tf32.tf32.f32 "                   \
      "{%0,%1,%2,%3}, {%4,%5,%6,%7}, {%8,%9}, {%0,%1,%2,%3};"                 \
      : "+f"((d)[0]), "+f"((d)[1]), "+f"((d)[2]), "+f"((d)[3])                \
      : "r"((a)[0]), "r"((a)[1]), "r"((a)[2]), "r"((a)[3]),                   \
        "r"((b)[0]), "r"((b)[1]))

#define BF16_ONES 0x3F803F80u  // bf16x2 {1.0, 1.0}

// ---------------------------------------------------------------------------
// tf32 QKV GEMM (R8-measured): tile 64x64, 8 warps (2m x 4n), double-buffered
// smem, register prefetch, one sync per k-step. Q pre-scaled by SCALE*log2e.
// ---------------------------------------------------------------------------
__global__ __launch_bounds__(256) void gemm_qkv_kernel(
    const float* __restrict__ A, const float* __restrict__ B,
    const float* __restrict__ bias) {
  const int Nc = 768;
  __shared__ u32 As[2][16][68];  // [buf][k][m]
  __shared__ u32 Bs[2][16][68];  // [buf][k][n]
  const int t = threadIdx.x;
  const int w = t >> 5, l = t & 31;
  const int wm = w >> 2, wn = w & 3;
  const int m0 = wm * 32, n0 = wn * 16;
  const int lk = l & 3, lm = l >> 2;
  const int bx = blockIdx.x, by = blockIdx.y;

  const int ar = t >> 2, ac = (t & 3) << 2;
  const int br = t >> 4, bc = (t & 15) << 2;
  const float* Aptr = A + (by * 64 + ar) * KDIM + ac;
  const float* Bptr = B + br * Nc + bx * 64 + bc;

  float c[2][2][4];
#pragma unroll
  for (int mt = 0; mt < 2; mt++)
#pragma unroll
    for (int nt = 0; nt < 2; nt++)
#pragma unroll
      for (int i = 0; i < 4; i++) c[mt][nt][i] = 0.f;

  {
    float4 av = *(const float4*)Aptr;
    float4 bv = *(const float4*)Bptr;
    As[0][ac + 0][ar] = tf32cvt(av.x);
    As[0][ac + 1][ar] = tf32cvt(av.y);
    As[0][ac + 2][ar] = tf32cvt(av.z);
    As[0][ac + 3][ar] = tf32cvt(av.w);
    Bs[0][br][bc + 0] = tf32cvt(bv.x);
    Bs[0][br][bc + 1] = tf32cvt(bv.y);
    Bs[0][br][bc + 2] = tf32cvt(bv.z);
    Bs[0][br][bc + 3] = tf32cvt(bv.w);
  }
  __syncthreads();

#pragma unroll
  for (int it = 0; it < 16; ++it) {
    const int buf = it & 1;
    float4 av, bv;
    if (it < 15) {
      av = *(const float4*)(Aptr + (it + 1) * 16);
      bv = *(const float4*)(Bptr + (it + 1) * 16 * Nc);
    }
#pragma unroll
    for (int kc = 0; kc < 2; kc++) {
      const int kq = kc * 8;
      u32 a[2][4], b[2][2];
#pragma unroll
      for (int mt = 0; mt < 2; mt++) {
        a[mt][0] = As[buf][kq + lk][m0 + mt * 16 + lm];
        a[mt][1] = As[buf][kq + lk][m0 + mt * 16 + lm + 8];
        a[mt][2] = As[buf][kq + lk + 4][m0 + mt * 16 + lm];
        a[mt][3] = As[buf][kq + lk + 4][m0 + mt * 16 + lm + 8];
      }
#pragma unroll
      for (int nt = 0; nt < 2; nt++) {
        b[nt][0] = Bs[buf][kq + lk][n0 + nt * 8 + lm];
        b[nt][1] = Bs[buf][kq + lk + 4][n0 + nt * 8 + lm];
      }
#pragma unroll
      for (int mt = 0; mt < 2; mt++)
#pragma unroll
        for (int nt = 0; nt < 2; nt++) MMATF32(c[mt][nt], a[mt], b[nt]);
    }
    if (it < 15) {
      const int nb = buf ^ 1;
      As[nb][ac + 0][ar] = tf32cvt(av.x);
      As[nb][ac + 1][ar] = tf32cvt(av.y);
      As[nb][ac + 2][ar] = tf32cvt(av.z);
      As[nb][ac + 3][ar] = tf32cvt(av.w);
      Bs[nb][br][bc + 0] = tf32cvt(bv.x);
      Bs[nb][br][bc + 1] = tf32cvt(bv.y);
      Bs[nb][br][bc + 2] = tf32cvt(bv.z);
      Bs[nb][br][bc + 3] = tf32cvt(bv.w);
    }
    __syncthreads();
  }

#pragma unroll
  for (int mt = 0; mt < 2; mt++) {
    const int row = by * 64 + m0 + mt * 16 + lm;
#pragma unroll
    for (int nt = 0; nt < 2; nt++) {
      const int col = bx * 64 + n0 + nt * 8 + 2 * lk;
      const float2 bv2 = *(const float2*)&bias[col];
      float v00 = c[mt][nt][0] + bv2.x, v01 = c[mt][nt][1] + bv2.y;
      float v10 = c[mt][nt][2] + bv2.x, v11 = c[mt][nt][3] + bv2.y;
      const int type = col >> 8, hd = col & 255;
      if (type == 0) {  // Q pre-scaled so QK MMA output is the ex2 argument
        v00 *= SCALE2; v01 *= SCALE2; v10 *= SCALE2; v11 *= SCALE2;
      }
      __nv_bfloat16* dst = (type == 0) ? g_qb : (type == 1) ? g_kb : g_vb;
      __nv_bfloat162 p0 = __floats2bfloat162_rn(v00, v01);
      __nv_bfloat162 p1 = __floats2bfloat162_rn(v10, v11);
      *(u32*)(dst + row * DMODEL + hd) = *(u32*)&p0;
      *(u32*)(dst + (row + 8) * DMODEL + hd) = *(u32*)&p1;
    }
  }
}

// ---------------------------------------------------------------------------
// Output GEMM: 32x64 block tile, 128 threads / 4 warps (2m x 2n), warp 16x32.
// Grid 512 blocks -> chip full (was 256 blocks = grid-starved at occ 20%).
// Same validated tf32 fragment indexing + double-buffer skeleton.
// ---------------------------------------------------------------------------
__global__ __launch_bounds__(128) void gemm_out_kernel(
    const float* __restrict__ A, const float* __restrict__ B,
    const float* __restrict__ bias, float* __restrict__ C) {
  const int Nc = 256;
  __shared__ u32 As[2][16][36];  // [buf][k][m], m=32 pad 36
  __shared__ u32 Bs[2][16][68];  // [buf][k][n]
  const int t = threadIdx.x;
  const int w = t >> 5, l = t & 31;
  const int wm = w >> 1, wn = w & 1;
  const int m0 = wm * 16, n0 = wn * 32;
  const int lk = l & 3, lm = l >> 2;
  const int bx = blockIdx.x, by = blockIdx.y;

  const int ar = t >> 2, ac = (t & 3) << 2;   // A: 32 rows x 4 chunks, 1/thread
  const int br = t >> 4, bc = (t & 15) << 2;  // B: rows br, br+8; 2/thread
  const float* Aptr = A + (by * 32 + ar) * KDIM + ac;
  const float* Bptr0 = B + br * Nc + bx * 64 + bc;
  const float* Bptr1 = B + (br + 8) * Nc + bx * 64 + bc;

  float c[4][4];
#pragma unroll
  for (int nt = 0; nt < 4; nt++)
#pragma unroll
    for (int i = 0; i < 4; i++) c[nt][i] = 0.f;

  {
    float4 av = *(const float4*)Aptr;
    float4 b0 = *(const float4*)Bptr0;
    float4 b1 = *(const float4*)Bptr1;
    As[0][ac + 0][ar] = tf32cvt(av.x);
    As[0][ac + 1][ar] = tf32cvt(av.y);
    As[0][ac + 2][ar] = tf32cvt(av.z);
    As[0][ac + 3][ar] = tf32cvt(av.w);
    Bs[0][br][bc + 0] = tf32cvt(b0.x);
    Bs[0][br][bc + 1] = tf32cvt(b0.y);
    Bs[0][br][bc + 2] = tf32cvt(b0.z);
    Bs[0][br][bc + 3] = tf32cvt(b0.w);
    Bs[0][br + 8][bc + 0] = tf32cvt(b1.x);
    Bs[0][br + 8][bc + 1] = tf32cvt(b1.y);
    Bs[0][br + 8][bc + 2] = tf32cvt(b1.z);
    Bs[0][br + 8][bc + 3] = tf32cvt(b1.w);
  }
  __syncthreads();

#pragma unroll
  for (int it = 0; it < 16; ++it) {
    const int buf = it & 1;
    float4 av, b0, b1;
    if (it < 15) {
      av = *(const float4*)(Aptr + (it + 1) * 16);
      b0 = *(const float4*)(Bptr0 + (it + 1) * 16 * Nc);
      b1 = *(const float4*)(Bptr1 + (it + 1) * 16 * Nc);
    }
#pragma unroll
    for (int kc = 0; kc < 2; kc++) {
      const int kq = kc * 8;
      u32 a[4], b[4][2];
      a[0] = As[buf][kq + lk][m0 + lm];
      a[1] = As[buf][kq + lk][m0 + lm + 8];
      a[2] = As[buf][kq + lk + 4][m0 + lm];
      a[3] = As[buf][kq + lk + 4][m0 + lm + 8];
#pragma unroll
      for (int nt = 0; nt < 4; nt++) {
        b[nt][0] = Bs[buf][kq + lk][n0 + nt * 8 + lm];
        b[nt][1] = Bs[buf][kq + lk + 4][n0 + nt * 8 + lm];
      }
#pragma unroll
      for (int nt = 0; nt < 4; nt++) MMATF32(c[nt], a, b[nt]);
    }
    if (it < 15) {
      const int nb = buf ^ 1;
      As[nb][ac + 0][ar] = tf32cvt(av.x);
      As[nb][ac + 1][ar] = tf32cvt(av.y);
      As[nb][ac + 2][ar] = tf32cvt(av.z);
      As[nb][ac + 3][ar] = tf32cvt(av.w);
      Bs[nb][br][bc + 0] = tf32cvt(b0.x);
      Bs[nb][br][bc + 1] = tf32cvt(b0.y);
      Bs[nb][br][bc + 2] = tf32cvt(b0.z);
      Bs[nb][br][bc + 3] = tf32cvt(b0.w);
      Bs[nb][br + 8][bc + 0] = tf32cvt(b1.x);
      Bs[nb][br + 8][bc + 1] = tf32cvt(b1.y);
      Bs[nb][br + 8][bc + 2] = tf32cvt(b1.z);
      Bs[nb][br + 8][bc + 3] = tf32cvt(b1.w);
    }
    __syncthreads();
  }

  {
    const int row = by * 32 + m0 + lm;
#pragma unroll
    for (int nt = 0; nt < 4; nt++) {
      const int col = bx * 64 + n0 + nt * 8 + 2 * lk;
      const float2 bv2 = *(const float2*)&bias[col];
      *(float2*)&C[row * Nc + col] =
          make_float2(c[nt][0] + bv2.x, c[nt][1] + bv2.y);
      *(float2*)&C[(row + 8) * Nc + col] =
          make_float2(c[nt][2] + bv2.x, c[nt][3] + bv2.y);
    }
  }
}

// ---------------------------------------------------------------------------
// pe_proj[h][n] = pe[n,:] @ Wpe[:,h] + bpe[h]
// ---------------------------------------------------------------------------
__global__ __launch_bounds__(256) void pe_proj_kernel(
    const float* __restrict__ pe, const float* __restrict__ Wpe,
    const float* __restrict__ bpe) {
  const int n = blockIdx.x * blockDim.x + threadIdx.x;
  if (n >= NTOK) return;
  float pr[16];
#pragma unroll
  for (int i = 0; i < 4; i++) {
    float4 v = *(const float4*)&pe[n * 16 + i * 4];
    pr[i * 4 + 0] = v.x; pr[i * 4 + 1] = v.y; pr[i * 4 + 2] = v.z; pr[i * 4 + 3] = v.w;
  }
#pragma unroll
  for (int h = 0; h < NHEAD; h++) {
    float s = __ldg(&bpe[h]);
#pragma unroll
    for (int d = 0; d < 16; d++) s += pr[d] * __ldg(&Wpe[d * NHEAD + h]);
    g_pe[h * NTOK + n] = s;
  }
}

// ---------------------------------------------------------------------------
// mma.sync flash attention (R12 WIN config) + __launch_bounds__(256,3) to
// guarantee 3 blocks/SM for MUFU/tensor overlap across more warps.
// ---------------------------------------------------------------------------
#define ROWB 40  // padded smem row: 40 bf16 = 80B

__global__ __launch_bounds__(256, 3) void attn_mma_kernel() {
  __shared__ __align__(16) __nv_bfloat16 sQ[128 * ROWB];
  __shared__ __align__(16) __nv_bfloat16 sK[128 * ROWB];
  __shared__ __align__(16) __nv_bfloat16 sV[128 * ROWB];
  __shared__ float sPe[128];  // stores -pe*log2e

  const int t = threadIdx.x;
  const int w = t >> 5, l = t & 31;
  const int h = blockIdx.y;
  const int q0 = blockIdx.x * 128;

  // ---- stage Q (128 rows x 32 bf16 = 512 uint4) ----
#pragma unroll
  for (int c = t; c < 512; c += 256) {
    const int r = c >> 2, p = c & 3;
    uint4 v = *(const uint4*)(g_qb + (q0 + r) * DMODEL + h * HEADD + p * 8);
    *(uint4*)(sQ + r * ROWB + p * 8) = v;
  }

  // ---- prefetch 128-key slab 0 ----
  const int u = t & 127, pr_r = u >> 2, pr_p = u & 3;
  const bool isK = t < 128;
  const __nv_bfloat16* kvsrc = isK ? g_kb : g_vb;
  uint4 kvr[4];
  float pe_reg = 0.f;
#pragma unroll
  for (int j = 0; j < 4; j++)
    kvr[j] = *(const uint4*)(kvsrc + (pr_r + 32 * j) * DMODEL + h * HEADD + pr_p * 8);
  if (isK) pe_reg = -g_pe[h * NTOK + t] * LOG2E;
  __syncthreads();

  // ---- Q fragments (held for whole kernel) ----
  u32 qa[2][4];
  {
    const int qrow = w * 16 + (l & 7) + ((l >> 3) & 1) * 8;
    const int qcol = (l >> 4) * 8;
    u32 qaddr = smem_u32(sQ) + (qrow * ROWB + qcol) * 2;
    LDSM4(qa[0], qaddr);
    LDSM4(qa[1], qaddr + 32);
  }

  float o[4][4];
#pragma unroll
  for (int nd = 0; nd < 4; nd++)
#pragma unroll
    for (int i = 0; i < 4; i++) o[nd][i] = 0.f;
  float ol[4] = {0.f, 0.f, 0.f, 0.f};  // l accumulator (ones-MMA)

  const u32 sKb = smem_u32(sK), sVb = smem_u32(sV);
  const int kl_row = (l & 7);
  const int kl_g = (l >> 3);

  for (int it = 0; it < 32; ++it) {
    // commit prefetched 128-key slab
    {
      __nv_bfloat16* dst = isK ? sK : sV;
#pragma unroll
      for (int j = 0; j < 4; j++)
        *(uint4*)(dst + (pr_r + 32 * j) * ROWB + pr_p * 8) = kvr[j];
      if (isK) sPe[t] = pe_reg;
    }
    __syncthreads();
    if (it + 1 < 32) {
      const int base = (it + 1) * 128;
#pragma unroll
      for (int j = 0; j < 4; j++)
        kvr[j] = *(const uint4*)(kvsrc + (base + pr_r + 32 * j) * DMODEL + h * HEADD + pr_p * 8);
      if (isK) pe_reg = -g_pe[h * NTOK + base + t] * LOG2E;
    }

#pragma unroll
    for (int half = 0; half < 2; ++half) {
      const int ro = half * 64;

      // ---- scores (bias in accumulator init) + ex2 -> P fragments ----
      u32 pa[4][4];
#pragma unroll
      for (int n = 0; n < 8; ++n) {
        u32 kb[4];
        u32 kaddr = sKb + ((ro + n * 8 + kl_row) * ROWB + kl_g * 8) * 2;
        LDSM4(kb, kaddr);
        float2 pe2 = *(const float2*)&sPe[ro + n * 8 + ((l & 3) << 1)];
        float c[4] = {pe2.x, pe2.y, pe2.x, pe2.y};  // = -pe*log2e
        MMA16816(c, qa[0], kb[0], kb[1]);
        MMA16816(c, qa[1], kb[2], kb[3]);
        float e0 = ex2(c[0]);
        float e1 = ex2(c[1]);
        float e2 = ex2(c[2]);
        float e3 = ex2(c[3]);
        __nv_bfloat162 p01 = __floats2bfloat162_rn(e0, e1);
        __nv_bfloat162 p23 = __floats2bfloat162_rn(e2, e3);
        pa[n >> 1][(n & 1) * 2 + 0] = *(u32*)&p01;
        pa[n >> 1][(n & 1) * 2 + 1] = *(u32*)&p23;
      }

      // ---- l += P @ ones ----
      MMA16816(ol, pa[0], BF16_ONES, BF16_ONES);
      MMA16816(ol, pa[1], BF16_ONES, BF16_ONES);
      MMA16816(ol, pa[2], BF16_ONES, BF16_ONES);
      MMA16816(ol, pa[3], BF16_ONES, BF16_ONES);

      // ---- PV: O[16x32] += P[16x64] @ V[64x32] ----
#pragma unroll
      for (int nd = 0; nd < 4; ++nd) {
        u32 vb0[4], vb1[4];
        u32 va0 = sVb + ((ro + kl_g * 8 + kl_row) * ROWB + nd * 8) * 2;
        u32 va1 = sVb + ((ro + 32 + kl_g * 8 + kl_row) * ROWB + nd * 8) * 2;
        LDSM4T(vb0, va0);
        LDSM4T(vb1, va1);
        MMA16816(o[nd], pa[0], vb0[0], vb0[1]);
        MMA16816(o[nd], pa[1], vb0[2], vb0[3]);
        MMA16816(o[nd], pa[2], vb1[0], vb1[1]);
        MMA16816(o[nd], pa[3], vb1[2], vb1[3]);
      }
    }
    __syncthreads();
  }

  const float inv0 = 1.f / ol[0];
  const float inv1 = 1.f / ol[2];

  const int row0 = q0 + w * 16 + (l >> 2);
  const int col0 = h * HEADD + ((l & 3) << 1);
#pragma unroll
  for (int nd = 0; nd < 4; ++nd) {
    *(float2*)&g_att[row0 * DMODEL + col0 + nd * 8] =
        make_float2(o[nd][0] * inv0, o[nd][1] * inv0);
    *(float2*)&g_att[(row0 + 8) * DMODEL + col0 + nd * 8] =
        make_float2(o[nd][2] * inv1, o[nd][3] * inv1);
  }
}

// ---------------------------------------------------------------------------
extern "C" void kernel_launch(void* const* d_in, const int* in_sizes, int n_in,
                              void* d_out, int out_size) {
  const float* x    = (const float*)d_in[0];
  const float* pe   = (const float*)d_in[1];
  const float* Wqkv = (const float*)d_in[2];
  const float* bqkv = (const float*)d_in[3];
  const float* Wpe  = (const float*)d_in[4];
  const float* bpe  = (const float*)d_in[5];
  const float* Wout = (const float*)d_in[6];
  const float* bout = (const float*)d_in[7];
  float* out = (float*)d_out;

  void* p_att = nullptr;
  cudaGetSymbolAddress(&p_att, g_att);

  gemm_qkv_kernel<<<dim3(12, 64), 256>>>(x, Wqkv, bqkv);
  pe_proj_kernel<<<16, 256>>>(pe, Wpe, bpe);
  attn_mma_kernel<<<dim3(32, 8), 256>>>();
  gemm_out_kernel<<<dim3(4, 128), 128>>>((const float*)p_att, Wout, bout, out);
}

// round 14
// speedup vs baseline: 1.1182x; 1.1182x over previous
#include <cuda_runtime.h>
#include <cuda_bf16.h>

#define NTOK 4096
#define DMODEL 256
#define NHEAD 8
#define HEADD 32
#define KDIM 256
#define SCALE 0.17677669529663689f
#define LOG2E 1.4426950408889634f
#define SCALE2 (SCALE * LOG2E)

typedef unsigned long long u64;
typedef unsigned int u32;

// Scratch (device globals — no allocation allowed)
__device__ float g_pe[NHEAD * NTOK];           // [h][n], stores -pe_proj*log2e
__device__ float g_att[NTOK * DMODEL];         // attention output fp32
__device__ __nv_bfloat16 g_qb[NTOK * DMODEL];  // Q bf16, PRE-SCALED by SCALE*log2e
__device__ __nv_bfloat16 g_kb[NTOK * DMODEL];  // K bf16 [n][h*32+d]
__device__ __nv_bfloat16 g_vb[NTOK * DMODEL];  // V bf16 [n][h*32+d]

// ---------------- helpers ----------------
__device__ __forceinline__ u32 smem_u32(const void* p) {
  u32 a;
  asm("{ .reg .u64 t; cvta.to.shared.u64 t, %1; cvt.u32.u64 %0, t; }" : "=r"(a) : "l"(p));
  return a;
}
__device__ __forceinline__ u32 tf32cvt(float f) {
  u32 r;
  asm("cvt.rna.tf32.f32 %0, %1;" : "=r"(r) : "f"(f));
  return r;
}
__device__ __forceinline__ float ex2(float x) {
  float y;
  asm("ex2.approx.f32 %0, %1;" : "=f"(y) : "f"(x));
  return y;
}
#define CP_ASYNC16(dst, src)                                                  \
  asm volatile("cp.async.cg.shared.global [%0], [%1], 16;" :: "r"(dst),       \
               "l"(src) : "memory")
#define CP_ASYNC4(dst, src)                                                   \
  asm volatile("cp.async.ca.shared.global [%0], [%1], 4;" :: "r"(dst),        \
               "l"(src) : "memory")
#define CP_COMMIT() asm volatile("cp.async.commit_group;" ::: "memory")
#define CP_WAIT0() asm volatile("cp.async.wait_group 0;" ::: "memory")
#define CP_WAIT1() asm volatile("cp.async.wait_group 1;" ::: "memory")
#define LDSM4(r, addr)                                                        \
  asm volatile("ldmatrix.sync.aligned.m8n8.x4.shared.b16 {%0,%1,%2,%3}, [%4];"\
               : "=r"((r)[0]), "=r"((r)[1]), "=r"((r)[2]), "=r"((r)[3])       \
               : "r"(addr))
#define LDSM4T(r, addr)                                                       \
  asm volatile(                                                               \
      "ldmatrix.sync.aligned.m8n8.x4.trans.shared.b16 {%0,%1,%2,%3}, [%4];"   \
      : "=r"((r)[0]), "=r"((r)[1]), "=r"((r)[2]), "=r"((r)[3])                \
      : "r"(addr))
#define MMA16816(d, a, b0, b1)                                                \
  asm volatile(                                                               \
      "mma.sync.aligned.m16n8k16.row.col.f32.bf16.bf16.f32 "                  \
      "{%0,%1,%2,%3}, {%4,%5,%6,%7}, {%8,%9}, {%0,%1,%2,%3};"                 \
      : "+f"((d)[0]), "+f"((d)[1]), "+f"((d)[2]), "+f"((d)[3])                \
      : "r"((a)[0]), "r"((a)[1]), "r"((a)[2]), "r"((a)[3]), "r"(b0), "r"(b1))
#define MMATF32(d, a, b)                                                      \
  asm volatile(                                                               \
      "mma.sync.aligned.m16n8k8.row.col.f32.tf32.tf32.f32 "                   \
      "{%0,%1,%2,%3}, {%4,%5,%6,%7}, {%8,%9}, {%0,%1,%2,%3};"                 \
      : "+f"((d)[0]), "+f"((d)[1]), "+f"((d)[2]), "+f"((d)[3])                \
      : "r"((a)[0]), "r"((a)[1]), "r"((a)[2]), "r"((a)[3]),                   \
        "r"((b)[0]), "r"((b)[1]))

#define BF16_ONES 0x3F803F80u  // bf16x2 {1.0, 1.0}

// ---------------------------------------------------------------------------
// tf32 GEMM (R12 winner, verbatim): tile 64x64, 8 warps (2m x 4n),
// double-buffered smem, register prefetch, one sync per k-step.
// ---------------------------------------------------------------------------
template <int QKV>
__global__ __launch_bounds__(256) void gemm_tf32_kernel(
    const float* __restrict__ A, const float* __restrict__ B,
    const float* __restrict__ bias, float* __restrict__ C, int Nc) {
  __shared__ u32 As[2][16][68];  // [buf][k][m]
  __shared__ u32 Bs[2][16][68];  // [buf][k][n]
  const int t = threadIdx.x;
  const int w = t >> 5, l = t & 31;
  const int wm = w >> 2, wn = w & 3;
  const int m0 = wm * 32, n0 = wn * 16;
  const int lk = l & 3, lm = l >> 2;
  const int bx = blockIdx.x, by = blockIdx.y;

  const int ar = t >> 2, ac = (t & 3) << 2;
  const int br = t >> 4, bc = (t & 15) << 2;
  const float* Aptr = A + (by * 64 + ar) * KDIM + ac;
  const float* Bptr = B + br * Nc + bx * 64 + bc;

  float c[2][2][4];
#pragma unroll
  for (int mt = 0; mt < 2; mt++)
#pragma unroll
    for (int nt = 0; nt < 2; nt++)
#pragma unroll
      for (int i = 0; i < 4; i++) c[mt][nt][i] = 0.f;

  {
    float4 av = *(const float4*)Aptr;
    float4 bv = *(const float4*)Bptr;
    As[0][ac + 0][ar] = tf32cvt(av.x);
    As[0][ac + 1][ar] = tf32cvt(av.y);
    As[0][ac + 2][ar] = tf32cvt(av.z);
    As[0][ac + 3][ar] = tf32cvt(av.w);
    Bs[0][br][bc + 0] = tf32cvt(bv.x);
    Bs[0][br][bc + 1] = tf32cvt(bv.y);
    Bs[0][br][bc + 2] = tf32cvt(bv.z);
    Bs[0][br][bc + 3] = tf32cvt(bv.w);
  }
  __syncthreads();

#pragma unroll
  for (int it = 0; it < 16; ++it) {
    const int buf = it & 1;
    float4 av, bv;
    if (it < 15) {
      av = *(const float4*)(Aptr + (it + 1) * 16);
      bv = *(const float4*)(Bptr + (it + 1) * 16 * Nc);
    }
#pragma unroll
    for (int kc = 0; kc < 2; kc++) {
      const int kq = kc * 8;
      u32 a[2][4], b[2][2];
#pragma unroll
      for (int mt = 0; mt < 2; mt++) {
        a[mt][0] = As[buf][kq + lk][m0 + mt * 16 + lm];
        a[mt][1] = As[buf][kq + lk][m0 + mt * 16 + lm + 8];
        a[mt][2] = As[buf][kq + lk + 4][m0 + mt * 16 + lm];
        a[mt][3] = As[buf][kq + lk + 4][m0 + mt * 16 + lm + 8];
      }
#pragma unroll
      for (int nt = 0; nt < 2; nt++) {
        b[nt][0] = Bs[buf][kq + lk][n0 + nt * 8 + lm];
        b[nt][1] = Bs[buf][kq + lk + 4][n0 + nt * 8 + lm];
      }
#pragma unroll
      for (int mt = 0; mt < 2; mt++)
#pragma unroll
        for (int nt = 0; nt < 2; nt++) MMATF32(c[mt][nt], a[mt], b[nt]);
    }
    if (it < 15) {
      const int nb = buf ^ 1;
      As[nb][ac + 0][ar] = tf32cvt(av.x);
      As[nb][ac + 1][ar] = tf32cvt(av.y);
      As[nb][ac + 2][ar] = tf32cvt(av.z);
      As[nb][ac + 3][ar] = tf32cvt(av.w);
      Bs[nb][br][bc + 0] = tf32cvt(bv.x);
      Bs[nb][br][bc + 1] = tf32cvt(bv.y);
      Bs[nb][br][bc + 2] = tf32cvt(bv.z);
      Bs[nb][br][bc + 3] = tf32cvt(bv.w);
    }
    __syncthreads();
  }

#pragma unroll
  for (int mt = 0; mt < 2; mt++) {
    const int row = by * 64 + m0 + mt * 16 + lm;
#pragma unroll
    for (int nt = 0; nt < 2; nt++) {
      const int col = bx * 64 + n0 + nt * 8 + 2 * lk;
      const float2 bv2 = *(const float2*)&bias[col];
      float v00 = c[mt][nt][0] + bv2.x, v01 = c[mt][nt][1] + bv2.y;
      float v10 = c[mt][nt][2] + bv2.x, v11 = c[mt][nt][3] + bv2.y;
      if (QKV) {
        const int type = col >> 8, hd = col & 255;
        if (type == 0) {  // Q pre-scaled so QK MMA output is the ex2 argument
          v00 *= SCALE2; v01 *= SCALE2; v10 *= SCALE2; v11 *= SCALE2;
        }
        __nv_bfloat16* dst = (type == 0) ? g_qb : (type == 1) ? g_kb : g_vb;
        __nv_bfloat162 p0 = __floats2bfloat162_rn(v00, v01);
        __nv_bfloat162 p1 = __floats2bfloat162_rn(v10, v11);
        *(u32*)(dst + row * DMODEL + hd) = *(u32*)&p0;
        *(u32*)(dst + (row + 8) * DMODEL + hd) = *(u32*)&p1;
      } else {
        *(float2*)&C[row * Nc + col] = make_float2(v00, v01);
        *(float2*)&C[(row + 8) * Nc + col] = make_float2(v10, v11);
      }
    }
  }
}

// ---------------------------------------------------------------------------
// pe_proj: stores -(pe@Wpe + bpe)*log2e so attention can cp.async it raw.
// ---------------------------------------------------------------------------
__global__ __launch_bounds__(256) void pe_proj_kernel(
    const float* __restrict__ pe, const float* __restrict__ Wpe,
    const float* __restrict__ bpe) {
  const int n = blockIdx.x * blockDim.x + threadIdx.x;
  if (n >= NTOK) return;
  float pr[16];
#pragma unroll
  for (int i = 0; i < 4; i++) {
    float4 v = *(const float4*)&pe[n * 16 + i * 4];
    pr[i * 4 + 0] = v.x; pr[i * 4 + 1] = v.y; pr[i * 4 + 2] = v.z; pr[i * 4 + 3] = v.w;
  }
#pragma unroll
  for (int h = 0; h < NHEAD; h++) {
    float s = __ldg(&bpe[h]);
#pragma unroll
    for (int d = 0; d < 16; d++) s += pr[d] * __ldg(&Wpe[d * NHEAD + h]);
    g_pe[h * NTOK + n] = -s * LOG2E;
  }
}

// ---------------------------------------------------------------------------
// mma.sync flash attention (R12 compute core) with cp.async K/V staging:
//  - double-buffered K/V via cp.async.cg (no staging registers at all)
//  - sQ region aliased as K buf1 after the one-time Q fragment load
//  - occ 3 blocks/SM now reachable without spill (launch_bounds(256,3))
// smem layout (bytes): [0,10240) Q then K-buf1 | [10240,20480) K-buf0 |
//   [20480,30720) V-buf0 | [30720,40960) V-buf1 | [40960,41984) pe[2][128]
// ---------------------------------------------------------------------------
#define SMB_K(buf) ((buf) ? 0 : 10240)
#define SMB_V(buf) (20480 + (buf) * 10240)
#define SMB_PE(buf) (40960 + (buf) * 512)

__global__ __launch_bounds__(256, 3) void attn_mma_kernel() {
  __shared__ __align__(16) char sm[41984];
  const u32 sb = smem_u32(sm);
  const int t = threadIdx.x;
  const int w = t >> 5, l = t & 31;
  const int h = blockIdx.y;
  const int q0 = blockIdx.x * 128;

  const int u = t & 127, pr_r = u >> 2, pr_p = u & 3;
  const bool isK = t < 128;

  // ---- issue slab 0 (K->buf0, V->buf0, pe->buf0) ----
  if (isK) {
#pragma unroll
    for (int j = 0; j < 4; j++)
      CP_ASYNC16(sb + SMB_K(0) + (pr_r + 32 * j) * 80 + pr_p * 16,
                 g_kb + (pr_r + 32 * j) * DMODEL + h * HEADD + pr_p * 8);
    CP_ASYNC4(sb + SMB_PE(0) + t * 4, g_pe + h * NTOK + t);
  } else {
#pragma unroll
    for (int j = 0; j < 4; j++)
      CP_ASYNC16(sb + SMB_V(0) + (pr_r + 32 * j) * 80 + pr_p * 16,
                 g_vb + (pr_r + 32 * j) * DMODEL + h * HEADD + pr_p * 8);
  }
  CP_COMMIT();

  // ---- stage Q into region [0,10240) ----
#pragma unroll
  for (int c = t; c < 512; c += 256) {
    const int r = c >> 2, p = c & 3;
    uint4 v = *(const uint4*)(g_qb + (q0 + r) * DMODEL + h * HEADD + p * 8);
    *(uint4*)(sm + r * 80 + p * 16) = v;
  }
  __syncthreads();

  // ---- Q fragments (held for whole kernel) ----
  u32 qa[2][4];
  {
    const int qrow = w * 16 + (l & 7) + ((l >> 3) & 1) * 8;
    const int qcol = (l >> 4) * 8;
    u32 qaddr = sb + qrow * 80 + qcol * 2;
    LDSM4(qa[0], qaddr);
    LDSM4(qa[1], qaddr + 32);
  }
  __syncthreads();  // Q region now reusable as K buf1

  float o[4][4];
#pragma unroll
  for (int nd = 0; nd < 4; nd++)
#pragma unroll
    for (int i = 0; i < 4; i++) o[nd][i] = 0.f;
  float ol[4] = {0.f, 0.f, 0.f, 0.f};

  const int kl_row = l & 7;
  const int kl_g = l >> 3;

  for (int it = 0; it < 32; ++it) {
    const int buf = it & 1;
    if (it + 1 < 32) {  // issue next slab into other buffer, keep 1 in flight
      const int base = (it + 1) * 128;
      if (isK) {
#pragma unroll
        for (int j = 0; j < 4; j++)
          CP_ASYNC16(sb + SMB_K(buf ^ 1) + (pr_r + 32 * j) * 80 + pr_p * 16,
                     g_kb + (base + pr_r + 32 * j) * DMODEL + h * HEADD + pr_p * 8);
        CP_ASYNC4(sb + SMB_PE(buf ^ 1) + t * 4, g_pe + h * NTOK + base + t);
      } else {
#pragma unroll
        for (int j = 0; j < 4; j++)
          CP_ASYNC16(sb + SMB_V(buf ^ 1) + (pr_r + 32 * j) * 80 + pr_p * 16,
                     g_vb + (base + pr_r + 32 * j) * DMODEL + h * HEADD + pr_p * 8);
      }
      CP_COMMIT();
      CP_WAIT1();  // slab `it` complete; slab `it+1` may stay in flight
    } else {
      CP_WAIT0();
    }
    __syncthreads();

    const u32 sKb = sb + SMB_K(buf);
    const u32 sVb = sb + SMB_V(buf);
    const float* pev = (const float*)(sm + SMB_PE(buf));

#pragma unroll
    for (int half = 0; half < 2; ++half) {
      const int ro = half * 64;

      // ---- scores (bias in accumulator init) + ex2 -> P fragments ----
      u32 pa[4][4];
#pragma unroll
      for (int n = 0; n < 8; ++n) {
        u32 kb[4];
        LDSM4(kb, sKb + (ro + n * 8 + kl_row) * 80 + kl_g * 16);
        float2 pe2 = *(const float2*)&pev[ro + n * 8 + ((l & 3) << 1)];
        float c[4] = {pe2.x, pe2.y, pe2.x, pe2.y};  // = -pe*log2e
        MMA16816(c, qa[0], kb[0], kb[1]);
        MMA16816(c, qa[1], kb[2], kb[3]);
        float e0 = ex2(c[0]);
        float e1 = ex2(c[1]);
        float e2 = ex2(c[2]);
        float e3 = ex2(c[3]);
        __nv_bfloat162 p01 = __floats2bfloat162_rn(e0, e1);
        __nv_bfloat162 p23 = __floats2bfloat162_rn(e2, e3);
        pa[n >> 1][(n & 1) * 2 + 0] = *(u32*)&p01;
        pa[n >> 1][(n & 1) * 2 + 1] = *(u32*)&p23;
      }

      // ---- l += P @ ones ----
      MMA16816(ol, pa[0], BF16_ONES, BF16_ONES);
      MMA16816(ol, pa[1], BF16_ONES, BF16_ONES);
      MMA16816(ol, pa[2], BF16_ONES, BF16_ONES);
      MMA16816(ol, pa[3], BF16_ONES, BF16_ONES);

      // ---- PV: O[16x32] += P[16x64] @ V[64x32] ----
#pragma unroll
      for (int nd = 0; nd < 4; ++nd) {
        u32 vb0[4], vb1[4];
        LDSM4T(vb0, sVb + (ro + kl_g * 8 + kl_row) * 80 + nd * 16);
        LDSM4T(vb1, sVb + (ro + 32 + kl_g * 8 + kl_row) * 80 + nd * 16);
        MMA16816(o[nd], pa[0], vb0[0], vb0[1]);
        MMA16816(o[nd], pa[1], vb0[2], vb0[3]);
        MMA16816(o[nd], pa[2], vb1[0], vb1[1]);
        MMA16816(o[nd], pa[3], vb1[2], vb1[3]);
      }
    }
    __syncthreads();  // buffer `buf` free before iter it+1 issues into it
  }

  const float inv0 = 1.f / ol[0];
  const float inv1 = 1.f / ol[2];

  const int row0 = q0 + w * 16 + (l >> 2);
  const int col0 = h * HEADD + ((l & 3) << 1);
#pragma unroll
  for (int nd = 0; nd < 4; ++nd) {
    *(float2*)&g_att[row0 * DMODEL + col0 + nd * 8] =
        make_float2(o[nd][0] * inv0, o[nd][1] * inv0);
    *(float2*)&g_att[(row0 + 8) * DMODEL + col0 + nd * 8] =
        make_float2(o[nd][2] * inv1, o[nd][3] * inv1);
  }
}

// ---------------------------------------------------------------------------
extern "C" void kernel_launch(void* const* d_in, const int* in_sizes, int n_in,
                              void* d_out, int out_size) {
  const float* x    = (const float*)d_in[0];
  const float* pe   = (const float*)d_in[1];
  const float* Wqkv = (const float*)d_in[2];
  const float* bqkv = (const float*)d_in[3];
  const float* Wpe  = (const float*)d_in[4];
  const float* bpe  = (const float*)d_in[5];
  const float* Wout = (const float*)d_in[6];
  const float* bout = (const float*)d_in[7];
  float* out = (float*)d_out;

  void* p_att = nullptr;
  cudaGetSymbolAddress(&p_att, g_att);

  gemm_tf32_kernel<1><<<dim3(12, 64), 256>>>(x, Wqkv, bqkv, nullptr, 768);
  pe_proj_kernel<<<16, 256>>>(pe, Wpe, bpe);
  attn_mma_kernel<<<dim3(32, 8), 256>>>();
  gemm_tf32_kernel<0><<<dim3(4, 64), 256>>>((const float*)p_att, Wout, bout, out, 256);
}

// round 15
// speedup vs baseline: 1.2259x; 1.0963x over previous
#include <cuda_runtime.h>
#include <cuda_bf16.h>

#define NTOK 4096
#define DMODEL 256
#define NHEAD 8
#define HEADD 32
#define KDIM 256
#define SCALE 0.17677669529663689f
#define LOG2E 1.4426950408889634f
#define SCALE2 (SCALE * LOG2E)

typedef unsigned long long u64;
typedef unsigned int u32;

// Scratch (device globals — no allocation allowed)
__device__ float g_pe[NHEAD * NTOK];           // [h][n], stores -pe_proj*log2e
__device__ float g_att[NTOK * DMODEL];         // attention output fp32
__device__ __nv_bfloat16 g_qb[NTOK * DMODEL];  // Q bf16, PRE-SCALED by SCALE*log2e
__device__ __nv_bfloat16 g_kb[NTOK * DMODEL];  // K bf16 [n][h*32+d]
__device__ __nv_bfloat16 g_vb[NTOK * DMODEL];  // V bf16 [n][h*32+d]

// ---------------- helpers ----------------
__device__ __forceinline__ u32 smem_u32(const void* p) {
  u32 a;
  asm("{ .reg .u64 t; cvta.to.shared.u64 t, %1; cvt.u32.u64 %0, t; }" : "=r"(a) : "l"(p));
  return a;
}
__device__ __forceinline__ float ex2(float x) {
  float y;
  asm("ex2.approx.f32 %0, %1;" : "=f"(y) : "f"(x));
  return y;
}
#define CP_ASYNC16(dst, src)                                                  \
  asm volatile("cp.async.cg.shared.global [%0], [%1], 16;" :: "r"(dst),       \
               "l"(src) : "memory")
#define CP_ASYNC4(dst, src)                                                   \
  asm volatile("cp.async.ca.shared.global [%0], [%1], 4;" :: "r"(dst),        \
               "l"(src) : "memory")
#define CP_COMMIT() asm volatile("cp.async.commit_group;" ::: "memory")
#define CP_WAIT0() asm volatile("cp.async.wait_group 0;" ::: "memory")
#define CP_WAIT1() asm volatile("cp.async.wait_group 1;" ::: "memory")
#define LDSM4(r, addr)                                                        \
  asm volatile("ldmatrix.sync.aligned.m8n8.x4.shared.b16 {%0,%1,%2,%3}, [%4];"\
               : "=r"((r)[0]), "=r"((r)[1]), "=r"((r)[2]), "=r"((r)[3])       \
               : "r"(addr))
#define LDSM4T(r, addr)                                                       \
  asm volatile(                                                               \
      "ldmatrix.sync.aligned.m8n8.x4.trans.shared.b16 {%0,%1,%2,%3}, [%4];"   \
      : "=r"((r)[0]), "=r"((r)[1]), "=r"((r)[2]), "=r"((r)[3])                \
      : "r"(addr))
#define MMA16816(d, a, b0, b1)                                                \
  asm volatile(                                                               \
      "mma.sync.aligned.m16n8k16.row.col.f32.bf16.bf16.f32 "                  \
      "{%0,%1,%2,%3}, {%4,%5,%6,%7}, {%8,%9}, {%0,%1,%2,%3};"                 \
      : "+f"((d)[0]), "+f"((d)[1]), "+f"((d)[2]), "+f"((d)[3])                \
      : "r"((a)[0]), "r"((a)[1]), "r"((a)[2]), "r"((a)[3]), "r"(b0), "r"(b1))
#define MMATF32(d, a, b)                                                      \
  asm volatile(                                                               \
      "mma.sync.aligned.m16n8k8.row.col.f32.tf32.tf32.f32 "                   \
      "{%0,%1,%2,%3}, {%4,%5,%6,%7}, {%8,%9}, {%0,%1,%2,%3};"                 \
      : "+f"((d)[0]), "+f"((d)[1]), "+f"((d)[2]), "+f"((d)[3])                \
      : "r"((a)[0]), "r"((a)[1]), "r"((a)[2]), "r"((a)[3]),                   \
        "r"((b)[0]), "r"((b)[1]))

#define BF16_ONES 0x3F803F80u  // bf16x2 {1.0, 1.0}

// ---------------------------------------------------------------------------
// tf32 GEMM with cp.async staging (no explicit cvt — MMA truncates fp32 bits
// to tf32). Tile 64x64, 8 warps (2m x 4n), double-buffered smem via
// commit/wait1 pipeline. A stored row-major [m][k] stride 20 (conflict-free
// gather: {20*lm+lk} distinct mod 32); B [k][n] stride 68 as before.
// ---------------------------------------------------------------------------
template <int QKV>
__global__ __launch_bounds__(256) void gemm_tf32_kernel(
    const float* __restrict__ A, const float* __restrict__ B,
    const float* __restrict__ bias, float* __restrict__ C, int Nc) {
  __shared__ __align__(16) u32 As[2][64][20];  // [buf][m][k]
  __shared__ __align__(16) u32 Bs[2][16][68];  // [buf][k][n]
  const int t = threadIdx.x;
  const int w = t >> 5, l = t & 31;
  const int wm = w >> 2, wn = w & 3;
  const int m0 = wm * 32, n0 = wn * 16;
  const int lk = l & 3, lm = l >> 2;
  const int bx = blockIdx.x, by = blockIdx.y;

  // cp.async staging map: A = 64 rows x 4 x 16B; B = 16 rows x 16 x 16B
  const int ar = t >> 2, apc = t & 3;
  const int br = t >> 4, bpc = t & 15;
  const float* Asrc = A + (by * 64 + ar) * KDIM + apc * 4;
  const float* Bsrc = B + br * Nc + bx * 64 + bpc * 4;
  const u32 sA = smem_u32(As), sB = smem_u32(Bs);
  const u32 adst = sA + ar * 80 + apc * 16;   // + buf*5120
  const u32 bdst = sB + br * 272 + bpc * 16;  // + buf*4352

  float c[2][2][4];
#pragma unroll
  for (int mt = 0; mt < 2; mt++)
#pragma unroll
    for (int nt = 0; nt < 2; nt++)
#pragma unroll
      for (int i = 0; i < 4; i++) c[mt][nt][i] = 0.f;

  // issue k-slab 0 into buf 0
  CP_ASYNC16(adst, Asrc);
  CP_ASYNC16(bdst, Bsrc);
  CP_COMMIT();

#pragma unroll
  for (int it = 0; it < 16; ++it) {
    const int buf = it & 1;
    if (it < 15) {  // issue next slab into other buffer; keep 1 in flight
      CP_ASYNC16(adst + (buf ^ 1) * 5120, Asrc + (it + 1) * 16);
      CP_ASYNC16(bdst + (buf ^ 1) * 4352, Bsrc + (it + 1) * 16 * Nc);
      CP_COMMIT();
      CP_WAIT1();
    } else {
      CP_WAIT0();
    }
    __syncthreads();

#pragma unroll
    for (int kc = 0; kc < 2; kc++) {
      const int kq = kc * 8;
      u32 a[2][4], b[2][2];
#pragma unroll
      for (int mt = 0; mt < 2; mt++) {
        a[mt][0] = As[buf][m0 + mt * 16 + lm][kq + lk];
        a[mt][1] = As[buf][m0 + mt * 16 + lm + 8][kq + lk];
        a[mt][2] = As[buf][m0 + mt * 16 + lm][kq + lk + 4];
        a[mt][3] = As[buf][m0 + mt * 16 + lm + 8][kq + lk + 4];
      }
#pragma unroll
      for (int nt = 0; nt < 2; nt++) {
        b[nt][0] = Bs[buf][kq + lk][n0 + nt * 8 + lm];
        b[nt][1] = Bs[buf][kq + lk + 4][n0 + nt * 8 + lm];
      }
#pragma unroll
      for (int mt = 0; mt < 2; mt++)
#pragma unroll
        for (int nt = 0; nt < 2; nt++) MMATF32(c[mt][nt], a[mt], b[nt]);
    }
    __syncthreads();  // buffer free before it+1 issues into it
  }

#pragma unroll
  for (int mt = 0; mt < 2; mt++) {
    const int row = by * 64 + m0 + mt * 16 + lm;
#pragma unroll
    for (int nt = 0; nt < 2; nt++) {
      const int col = bx * 64 + n0 + nt * 8 + 2 * lk;
      const float2 bv2 = *(const float2*)&bias[col];
      float v00 = c[mt][nt][0] + bv2.x, v01 = c[mt][nt][1] + bv2.y;
      float v10 = c[mt][nt][2] + bv2.x, v11 = c[mt][nt][3] + bv2.y;
      if (QKV) {
        const int type = col >> 8, hd = col & 255;
        if (type == 0) {  // Q pre-scaled so QK MMA output is the ex2 argument
          v00 *= SCALE2; v01 *= SCALE2; v10 *= SCALE2; v11 *= SCALE2;
        }
        __nv_bfloat16* dst = (type == 0) ? g_qb : (type == 1) ? g_kb : g_vb;
        __nv_bfloat162 p0 = __floats2bfloat162_rn(v00, v01);
        __nv_bfloat162 p1 = __floats2bfloat162_rn(v10, v11);
        *(u32*)(dst + row * DMODEL + hd) = *(u32*)&p0;
        *(u32*)(dst + (row + 8) * DMODEL + hd) = *(u32*)&p1;
      } else {
        *(float2*)&C[row * Nc + col] = make_float2(v00, v01);
        *(float2*)&C[(row + 8) * Nc + col] = make_float2(v10, v11);
      }
    }
  }
}

// ---------------------------------------------------------------------------
// pe_proj: stores -(pe@Wpe + bpe)*log2e so attention can cp.async it raw.
// ---------------------------------------------------------------------------
__global__ __launch_bounds__(256) void pe_proj_kernel(
    const float* __restrict__ pe, const float* __restrict__ Wpe,
    const float* __restrict__ bpe) {
  const int n = blockIdx.x * blockDim.x + threadIdx.x;
  if (n >= NTOK) return;
  float pr[16];
#pragma unroll
  for (int i = 0; i < 4; i++) {
    float4 v = *(const float4*)&pe[n * 16 + i * 4];
    pr[i * 4 + 0] = v.x; pr[i * 4 + 1] = v.y; pr[i * 4 + 2] = v.z; pr[i * 4 + 3] = v.w;
  }
#pragma unroll
  for (int h = 0; h < NHEAD; h++) {
    float s = __ldg(&bpe[h]);
#pragma unroll
    for (int d = 0; d < 16; d++) s += pr[d] * __ldg(&Wpe[d * NHEAD + h]);
    g_pe[h * NTOK + n] = -s * LOG2E;
  }
}

// ---------------------------------------------------------------------------
// mma.sync flash attention (R14 winner, verbatim): cp.async K/V staging,
// double-buffered, Q-region aliased as K buf1, occ 3.
// smem layout (bytes): [0,10240) Q then K-buf1 | [10240,20480) K-buf0 |
//   [20480,30720) V-buf0 | [30720,40960) V-buf1 | [40960,41984) pe[2][128]
// ---------------------------------------------------------------------------
#define SMB_K(buf) ((buf) ? 0 : 10240)
#define SMB_V(buf) (20480 + (buf) * 10240)
#define SMB_PE(buf) (40960 + (buf) * 512)

__global__ __launch_bounds__(256, 3) void attn_mma_kernel() {
  __shared__ __align__(16) char sm[41984];
  const u32 sb = smem_u32(sm);
  const int t = threadIdx.x;
  const int w = t >> 5, l = t & 31;
  const int h = blockIdx.y;
  const int q0 = blockIdx.x * 128;

  const int u = t & 127, pr_r = u >> 2, pr_p = u & 3;
  const bool isK = t < 128;

  // ---- issue slab 0 (K->buf0, V->buf0, pe->buf0) ----
  if (isK) {
#pragma unroll
    for (int j = 0; j < 4; j++)
      CP_ASYNC16(sb + SMB_K(0) + (pr_r + 32 * j) * 80 + pr_p * 16,
                 g_kb + (pr_r + 32 * j) * DMODEL + h * HEADD + pr_p * 8);
    CP_ASYNC4(sb + SMB_PE(0) + t * 4, g_pe + h * NTOK + t);
  } else {
#pragma unroll
    for (int j = 0; j < 4; j++)
      CP_ASYNC16(sb + SMB_V(0) + (pr_r + 32 * j) * 80 + pr_p * 16,
                 g_vb + (pr_r + 32 * j) * DMODEL + h * HEADD + pr_p * 8);
  }
  CP_COMMIT();

  // ---- stage Q into region [0,10240) ----
#pragma unroll
  for (int c = t; c < 512; c += 256) {
    const int r = c >> 2, p = c & 3;
    uint4 v = *(const uint4*)(g_qb + (q0 + r) * DMODEL + h * HEADD + p * 8);
    *(uint4*)(sm + r * 80 + p * 16) = v;
  }
  __syncthreads();

  // ---- Q fragments (held for whole kernel) ----
  u32 qa[2][4];
  {
    const int qrow = w * 16 + (l & 7) + ((l >> 3) & 1) * 8;
    const int qcol = (l >> 4) * 8;
    u32 qaddr = sb + qrow * 80 + qcol * 2;
    LDSM4(qa[0], qaddr);
    LDSM4(qa[1], qaddr + 32);
  }
  __syncthreads();  // Q region now reusable as K buf1

  float o[4][4];
#pragma unroll
  for (int nd = 0; nd < 4; nd++)
#pragma unroll
    for (int i = 0; i < 4; i++) o[nd][i] = 0.f;
  float ol[4] = {0.f, 0.f, 0.f, 0.f};

  const int kl_row = l & 7;
  const int kl_g = l >> 3;

  for (int it = 0; it < 32; ++it) {
    const int buf = it & 1;
    if (it + 1 < 32) {  // issue next slab into other buffer, keep 1 in flight
      const int base = (it + 1) * 128;
      if (isK) {
#pragma unroll
        for (int j = 0; j < 4; j++)
          CP_ASYNC16(sb + SMB_K(buf ^ 1) + (pr_r + 32 * j) * 80 + pr_p * 16,
                     g_kb + (base + pr_r + 32 * j) * DMODEL + h * HEADD + pr_p * 8);
        CP_ASYNC4(sb + SMB_PE(buf ^ 1) + t * 4, g_pe + h * NTOK + base + t);
      } else {
#pragma unroll
        for (int j = 0; j < 4; j++)
          CP_ASYNC16(sb + SMB_V(buf ^ 1) + (pr_r + 32 * j) * 80 + pr_p * 16,
                     g_vb + (base + pr_r + 32 * j) * DMODEL + h * HEADD + pr_p * 8);
      }
      CP_COMMIT();
      CP_WAIT1();
    } else {
      CP_WAIT0();
    }
    __syncthreads();

    const u32 sKb = sb + SMB_K(buf);
    const u32 sVb = sb + SMB_V(buf);
    const float* pev = (const float*)(sm + SMB_PE(buf));

#pragma unroll
    for (int half = 0; half < 2; ++half) {
      const int ro = half * 64;

      // ---- scores (bias in accumulator init) + ex2 -> P fragments ----
      u32 pa[4][4];
#pragma unroll
      for (int n = 0; n < 8; ++n) {
        u32 kb[4];
        LDSM4(kb, sKb + (ro + n * 8 + kl_row) * 80 + kl_g * 16);
        float2 pe2 = *(const float2*)&pev[ro + n * 8 + ((l & 3) << 1)];
        float c[4] = {pe2.x, pe2.y, pe2.x, pe2.y};  // = -pe*log2e
        MMA16816(c, qa[0], kb[0], kb[1]);
        MMA16816(c, qa[1], kb[2], kb[3]);
        float e0 = ex2(c[0]);
        float e1 = ex2(c[1]);
        float e2 = ex2(c[2]);
        float e3 = ex2(c[3]);
        __nv_bfloat162 p01 = __floats2bfloat162_rn(e0, e1);
        __nv_bfloat162 p23 = __floats2bfloat162_rn(e2, e3);
        pa[n >> 1][(n & 1) * 2 + 0] = *(u32*)&p01;
        pa[n >> 1][(n & 1) * 2 + 1] = *(u32*)&p23;
      }

      // ---- l += P @ ones ----
      MMA16816(ol, pa[0], BF16_ONES, BF16_ONES);
      MMA16816(ol, pa[1], BF16_ONES, BF16_ONES);
      MMA16816(ol, pa[2], BF16_ONES, BF16_ONES);
      MMA16816(ol, pa[3], BF16_ONES, BF16_ONES);

      // ---- PV: O[16x32] += P[16x64] @ V[64x32] ----
#pragma unroll
      for (int nd = 0; nd < 4; ++nd) {
        u32 vb0[4], vb1[4];
        LDSM4T(vb0, sVb + (ro + kl_g * 8 + kl_row) * 80 + nd * 16);
        LDSM4T(vb1, sVb + (ro + 32 + kl_g * 8 + kl_row) * 80 + nd * 16);
        MMA16816(o[nd], pa[0], vb0[0], vb0[1]);
        MMA16816(o[nd], pa[1], vb0[2], vb0[3]);
        MMA16816(o[nd], pa[2], vb1[0], vb1[1]);
        MMA16816(o[nd], pa[3], vb1[2], vb1[3]);
      }
    }
    __syncthreads();
  }

  const float inv0 = 1.f / ol[0];
  const float inv1 = 1.f / ol[2];

  const int row0 = q0 + w * 16 + (l >> 2);
  const int col0 = h * HEADD + ((l & 3) << 1);
#pragma unroll
  for (int nd = 0; nd < 4; ++nd) {
    *(float2*)&g_att[row0 * DMODEL + col0 + nd * 8] =
        make_float2(o[nd][0] * inv0, o[nd][1] * inv0);
    *(float2*)&g_att[(row0 + 8) * DMODEL + col0 + nd * 8] =
        make_float2(o[nd][2] * inv1, o[nd][3] * inv1);
  }
}

// ---------------------------------------------------------------------------
extern "C" void kernel_launch(void* const* d_in, const int* in_sizes, int n_in,
                              void* d_out, int out_size) {
  const float* x    = (const float*)d_in[0];
  const float* pe   = (const float*)d_in[1];
  const float* Wqkv = (const float*)d_in[2];
  const float* bqkv = (const float*)d_in[3];
  const float* Wpe  = (const float*)d_in[4];
  const float* bpe  = (const float*)d_in[5];
  const float* Wout = (const float*)d_in[6];
  const float* bout = (const float*)d_in[7];
  float* out = (float*)d_out;

  void* p_att = nullptr;
  cudaGetSymbolAddress(&p_att, g_att);

  gemm_tf32_kernel<1><<<dim3(12, 64), 256>>>(x, Wqkv, bqkv, nullptr, 768);
  pe_proj_kernel<<<16, 256>>>(pe, Wpe, bpe);
  attn_mma_kernel<<<dim3(32, 8), 256>>>();
  gemm_tf32_kernel<0><<<dim3(4, 64), 256>>>((const float*)p_att, Wout, bout, out, 256);
}